// round 9
// baseline (speedup 1.0000x reference)
#include <cuda_runtime.h>
#include <cuda_fp16.h>

#define NN   50000
#define EE   1600000
#define DD   128
#define KK   16
#define ALPHA_F 0.05f
#define CW_F    (0.95f / 16.0f)
#define NPAD 50048
#define NBLK 49            // ceil(NN/1024)

// packed f32x2 fused-multiply-add (SASS FFMA2) — PTX-only form
#define FMA_F32X2(d, a, b, c) \
    asm("fma.rn.f32x2 %0, %1, %2, %3;" : "=l"(d) : "l"(a), "l"(b), "l"(c))

__device__ __forceinline__ unsigned long long pack_f32x2(float lo, float hi) {
    union { float2 f; unsigned long long u; } p;
    p.f = make_float2(lo, hi);
    return p.u;
}
__device__ __forceinline__ float2 unpack_f32x2(unsigned long long v) {
    union { float2 f; unsigned long long u; } p;
    p.u = v;
    return p.f;
}

// -------------------- scratch (static device globals; no allocs) ------------
__device__ uint2 g_x16A[NPAD * 32];     // fp16 features ping
__device__ uint2 g_x16B[NPAD * 32];     // fp16 features pong
__device__ float g_h [NPAD * DD];       // fp32 h accumulator
__device__ int   g_deg[NN];
__device__ float g_dinv[NN];
__device__ int   g_rowptr[NN + 1];
__device__ int   g_cursor[NN];
__device__ int2  g_edge[EE];            // (col, bitcast weight)
__device__ int   g_bsum[NBLK];
__device__ int   g_boff[NBLK];

// -------------------- K1: init ----------------------------------------------
__global__ void initk_kernel() {
    int v = blockIdx.x * blockDim.x + threadIdx.x;
    if (v < NN) { g_deg[v] = 1; g_cursor[v] = 0; }
}

// -------------------- K2: degree count (int4 over dst) ----------------------
__global__ void count_deg_kernel(const int4* __restrict__ dst4) {
    for (int e = blockIdx.x * blockDim.x + threadIdx.x; e < EE / 4;
         e += gridDim.x * blockDim.x) {
        int4 d = __ldg(&dst4[e]);
        atomicAdd(&g_deg[d.x], 1);
        atomicAdd(&g_deg[d.y], 1);
        atomicAdd(&g_deg[d.z], 1);
        atomicAdd(&g_deg[d.w], 1);
    }
}

// -------------------- K3: dinv + fp16 x0 + h init ----------------------------
__global__ void prep3_kernel(const float* __restrict__ x0) {
    int idx = blockIdx.x * blockDim.x + threadIdx.x;    // float4 group index
    const int total = NN * 32;
    if (idx < total) {
        float4 v = ((const float4*)x0)[idx];
        __half2 p01 = __floats2half2_rn(v.x, v.y);
        __half2 p23 = __floats2half2_rn(v.z, v.w);
        uint2 o;
        o.x = *(unsigned int*)&p01;
        o.y = *(unsigned int*)&p23;
        g_x16A[idx] = o;
        float4 hv;
        hv.x = ALPHA_F * v.x; hv.y = ALPHA_F * v.y;
        hv.z = ALPHA_F * v.z; hv.w = ALPHA_F * v.w;
        ((float4*)g_h)[idx] = hv;
    }
    if (idx < NN) g_dinv[idx] = rsqrtf((float)g_deg[idx]);
}

// -------------------- K4-K6: 3-phase scan ------------------------------------
__device__ __forceinline__ int block_scan_inc(int v, int tid) {
    __shared__ int ws[32];
    const int lane = tid & 31, wid = tid >> 5;
    int x = v;
    #pragma unroll
    for (int d = 1; d < 32; d <<= 1) {
        int y = __shfl_up_sync(0xffffffffu, x, d);
        if (lane >= d) x += y;
    }
    if (lane == 31) ws[wid] = x;
    __syncthreads();
    if (wid == 0) {
        int s = ws[lane];
        int t = s;
        #pragma unroll
        for (int d = 1; d < 32; d <<= 1) {
            int y = __shfl_up_sync(0xffffffffu, t, d);
            if (lane >= d) t += y;
        }
        ws[lane] = t - s;
    }
    __syncthreads();
    return x + ws[wid];
}

__global__ void scan1_kernel() {
    __shared__ int ws[32];
    int tid = threadIdx.x;
    int i = blockIdx.x * 1024 + tid;
    int v = (i < NN) ? (g_deg[i] - 1) : 0;
    #pragma unroll
    for (int d = 16; d > 0; d >>= 1) v += __shfl_down_sync(0xffffffffu, v, d);
    if ((tid & 31) == 0) ws[tid >> 5] = v;
    __syncthreads();
    if (tid < 32) {
        int s = ws[tid];
        #pragma unroll
        for (int d = 16; d > 0; d >>= 1) s += __shfl_down_sync(0xffffffffu, s, d);
        if (tid == 0) g_bsum[blockIdx.x] = s;
    }
}

__global__ void scan2_kernel() {
    int tid = threadIdx.x;
    int v = (tid < NBLK) ? g_bsum[tid] : 0;
    int inc = block_scan_inc(v, tid);
    if (tid < NBLK) g_boff[tid] = inc - v;
    if (tid == 0) g_rowptr[NN] = EE;
}

__global__ void scan3_kernel() {
    int tid = threadIdx.x;
    int i = blockIdx.x * 1024 + tid;
    int v = (i < NN) ? (g_deg[i] - 1) : 0;
    int inc = block_scan_inc(v, tid);
    if (i < NN) g_rowptr[i] = inc - v + g_boff[blockIdx.x];
}

// -------------------- K7: CSR scatter (int4 edge reads) ----------------------
__global__ void scatter_kernel(const int4* __restrict__ src4,
                               const int4* __restrict__ dst4) {
    for (int e = blockIdx.x * blockDim.x + threadIdx.x; e < EE / 4;
         e += gridDim.x * blockDim.x) {
        int4 s = __ldg(&src4[e]);
        int4 d = __ldg(&dst4[e]);
        {
            int pos = g_rowptr[d.x] + atomicAdd(&g_cursor[d.x], 1);
            g_edge[pos] = make_int2(s.x, __float_as_int(g_dinv[s.x] * g_dinv[d.x]));
        }
        {
            int pos = g_rowptr[d.y] + atomicAdd(&g_cursor[d.y], 1);
            g_edge[pos] = make_int2(s.y, __float_as_int(g_dinv[s.y] * g_dinv[d.y]));
        }
        {
            int pos = g_rowptr[d.z] + atomicAdd(&g_cursor[d.z], 1);
            g_edge[pos] = make_int2(s.z, __float_as_int(g_dinv[s.z] * g_dinv[d.z]));
        }
        {
            int pos = g_rowptr[d.w] + atomicAdd(&g_cursor[d.w], 1);
            g_edge[pos] = make_int2(s.w, __float_as_int(g_dinv[s.w] * g_dinv[d.w]));
        }
    }
}

// -------------------- hop: one warp per node, lane owns 4 fp16 features -----
__device__ __forceinline__ void acc_edge(float4& acc, uint2 r, float w) {
    float2 f01 = __half22float2(*(__half2*)&r.x);
    float2 f23 = __half22float2(*(__half2*)&r.y);
    acc.x += w * f01.x; acc.y += w * f01.y;
    acc.z += w * f23.x; acc.w += w * f23.y;
}

__global__ void __launch_bounds__(256)
hop_kernel(const uint2* __restrict__ xin, uint2* __restrict__ xout,
           float* __restrict__ h) {
    const int warp = (blockIdx.x * blockDim.x + threadIdx.x) >> 5;
    const int lane = threadIdx.x & 31;
    if (warp >= NN) return;

    const float dv = g_dinv[warp];
    uint2 xr = __ldg(&xin[warp * 32 + lane]);
    float4 acc = {0.f, 0.f, 0.f, 0.f};
    acc_edge(acc, xr, dv * dv);

    const int start = g_rowptr[warp];
    const int len   = g_deg[warp] - 1;

    for (int base = 0; base < len; base += 32) {
        int idx = start + base + lane;
        int   c = 0;
        float w = 0.0f;
        if (base + lane < len) {
            int2 e = __ldg(&g_edge[idx]);
            c = e.x;
            w = __int_as_float(e.y);
        }
        int rem = len - base; if (rem > 32) rem = 32;
        int j = 0;
        for (; j + 8 <= rem; j += 8) {
            int   s0 = __shfl_sync(0xffffffffu, c, j + 0);
            int   s1 = __shfl_sync(0xffffffffu, c, j + 1);
            int   s2 = __shfl_sync(0xffffffffu, c, j + 2);
            int   s3 = __shfl_sync(0xffffffffu, c, j + 3);
            int   s4 = __shfl_sync(0xffffffffu, c, j + 4);
            int   s5 = __shfl_sync(0xffffffffu, c, j + 5);
            int   s6 = __shfl_sync(0xffffffffu, c, j + 6);
            int   s7 = __shfl_sync(0xffffffffu, c, j + 7);
            float w0 = __shfl_sync(0xffffffffu, w, j + 0);
            float w1 = __shfl_sync(0xffffffffu, w, j + 1);
            float w2 = __shfl_sync(0xffffffffu, w, j + 2);
            float w3 = __shfl_sync(0xffffffffu, w, j + 3);
            float w4 = __shfl_sync(0xffffffffu, w, j + 4);
            float w5 = __shfl_sync(0xffffffffu, w, j + 5);
            float w6 = __shfl_sync(0xffffffffu, w, j + 6);
            float w7 = __shfl_sync(0xffffffffu, w, j + 7);
            uint2 v0 = __ldg(&xin[s0 * 32 + lane]);
            uint2 v1 = __ldg(&xin[s1 * 32 + lane]);
            uint2 v2 = __ldg(&xin[s2 * 32 + lane]);
            uint2 v3 = __ldg(&xin[s3 * 32 + lane]);
            uint2 v4 = __ldg(&xin[s4 * 32 + lane]);
            uint2 v5 = __ldg(&xin[s5 * 32 + lane]);
            uint2 v6 = __ldg(&xin[s6 * 32 + lane]);
            uint2 v7 = __ldg(&xin[s7 * 32 + lane]);
            acc_edge(acc, v0, w0);
            acc_edge(acc, v1, w1);
            acc_edge(acc, v2, w2);
            acc_edge(acc, v3, w3);
            acc_edge(acc, v4, w4);
            acc_edge(acc, v5, w5);
            acc_edge(acc, v6, w6);
            acc_edge(acc, v7, w7);
        }
        for (; j < rem; j++) {
            int   s0 = __shfl_sync(0xffffffffu, c, j);
            float w0 = __shfl_sync(0xffffffffu, w, j);
            uint2 v0 = __ldg(&xin[s0 * 32 + lane]);
            acc_edge(acc, v0, w0);
        }
    }

    __half2 o01 = __floats2half2_rn(acc.x, acc.y);
    __half2 o23 = __floats2half2_rn(acc.z, acc.w);
    uint2 ow;
    ow.x = *(unsigned int*)&o01;
    ow.y = *(unsigned int*)&o23;
    xout[warp * 32 + lane] = ow;

    float4 hv = ((float4*)h)[warp * 32 + lane];
    hv.x += CW_F * acc.x; hv.y += CW_F * acc.y;
    hv.z += CW_F * acc.z; hv.w += CW_F * acc.w;
    ((float4*)h)[warp * 32 + lane] = hv;
}

// -------------------- FFMA2 GEMM: out = h @ W^T + bias -----------------------
// W is [D_OUT, D_IN] row-major -> thread o reads its own row directly.
#define GEMM_NODES 64
__global__ void __launch_bounds__(128)
gemm_kernel(const float* __restrict__ h, const float* __restrict__ W,
            const float* __restrict__ bias, float* __restrict__ out) {
    __shared__ unsigned long long sh2[GEMM_NODES * 64];   // 32 KB, packed pairs

    const int o = threadIdx.x;

    unsigned long long w2[64];
    const float4* wrow = (const float4*)(W + o * DD);
    #pragma unroll
    for (int q = 0; q < 32; q++) {
        float4 v = __ldg(&wrow[q]);
        w2[2 * q]     = pack_f32x2(v.x, v.y);
        w2[2 * q + 1] = pack_f32x2(v.z, v.w);
    }
    const float b = __ldg(&bias[o]);

    const int node0 = blockIdx.x * GEMM_NODES;
    const float4* h4 = (const float4*)(h + node0 * DD);   // NPAD padding covers tail

    #pragma unroll
    for (int s = threadIdx.x; s < GEMM_NODES * 32; s += 128) {
        float4 v = __ldg(&h4[s]);
        sh2[2 * s]     = pack_f32x2(v.x, v.y);
        sh2[2 * s + 1] = pack_f32x2(v.z, v.w);
    }
    __syncthreads();

    for (int nn = 0; nn < GEMM_NODES; nn++) {
        int node = node0 + nn;
        if (node >= NN) break;
        const unsigned long long* row = &sh2[nn * 64];
        unsigned long long a0 = 0ull, a1 = 0ull, a2 = 0ull, a3 = 0ull;
        #pragma unroll
        for (int g = 0; g < 64; g += 4) {
            FMA_F32X2(a0, row[g + 0], w2[g + 0], a0);
            FMA_F32X2(a1, row[g + 1], w2[g + 1], a1);
            FMA_F32X2(a2, row[g + 2], w2[g + 2], a2);
            FMA_F32X2(a3, row[g + 3], w2[g + 3], a3);
        }
        float2 f0 = unpack_f32x2(a0);
        float2 f1 = unpack_f32x2(a1);
        float2 f2 = unpack_f32x2(a2);
        float2 f3 = unpack_f32x2(a3);
        float r = b + ((f0.x + f0.y) + (f1.x + f1.y))
                    + ((f2.x + f2.y) + (f3.x + f3.y));
        out[node * DD + o] = r;
    }
}

// -------------------- launch -------------------------------------------------
extern "C" void kernel_launch(void* const* d_in, const int* in_sizes, int n_in,
                              void* d_out, int out_size) {
    const float* x0   = (const float*)d_in[0];
    const int*   ei   = (const int*)  d_in[1];
    const float* W    = (const float*)d_in[2];
    const float* bias = (const float*)d_in[3];
    const int4* src4 = (const int4*)ei;
    const int4* dst4 = (const int4*)(ei + EE);
    float* out = (float*)d_out;

    void *pA, *pB, *ph;
    cudaGetSymbolAddress(&pA, g_x16A);
    cudaGetSymbolAddress(&pB, g_x16B);
    cudaGetSymbolAddress(&ph, g_h);
    uint2* xA = (uint2*)pA;
    uint2* xB = (uint2*)pB;
    float* h  = (float*)ph;

    initk_kernel<<<(NN + 1023) / 1024, 1024>>>();
    count_deg_kernel<<<1024, 256>>>(dst4);
    prep3_kernel<<<(NN * 32 + 255) / 256, 256>>>(x0);
    scan1_kernel<<<NBLK, 1024>>>();
    scan2_kernel<<<1, 1024>>>();
    scan3_kernel<<<NBLK, 1024>>>();
    scatter_kernel<<<1024, 256>>>(src4, dst4);

    const uint2* xin = xA;
    uint2* xout = xB;
    for (int k = 0; k < KK; k++) {
        hop_kernel<<<(NN + 7) / 8, 256>>>(xin, xout, h);
        xin  = xout;
        xout = (xout == xB) ? xA : xB;
    }

    gemm_kernel<<<(NN + GEMM_NODES - 1) / GEMM_NODES, 128>>>(h, W, bias, out);
}

// round 11
// speedup vs baseline: 1.0823x; 1.0823x over previous
#include <cuda_runtime.h>
#include <cuda_fp16.h>

#define NN   50000
#define EE   1600000
#define DD   128
#define KK   16
#define ALPHA_F 0.05f
#define CW_F    (0.95f / 16.0f)
#define NPAD 50048
#define NBLK 49            // ceil(NN/1024)

// -------------------- scratch (static device globals; no allocs) ------------
__device__ uint2 g_x16A[NPAD * 32];     // fp16 features ping
__device__ uint2 g_x16B[NPAD * 32];     // fp16 features pong
__device__ float g_h [NPAD * DD];       // fp32 h accumulator (rows >= NN stay 0)
__device__ int   g_deg[NN];             // edge in-degree (NO self loop); 0 at entry
__device__ float g_dinv[NN];
__device__ int   g_rowptr[NN + 1];
__device__ int   g_cursor[NN];
__device__ int2  g_edge[EE];            // (col, bitcast weight)
__device__ int   g_bsum[NBLK];

// -------------------- L1: degree count (deg starts at 0) --------------------
__global__ void count_deg_kernel(const int* __restrict__ dst) {
    for (int e = blockIdx.x * blockDim.x + threadIdx.x; e < EE;
         e += gridDim.x * blockDim.x) {
        atomicAdd(&g_deg[dst[e]], 1);
    }
}

// -------------------- L2: cursor + dinv + fp16 x0 + h init ------------------
__global__ void prep_kernel(const float* __restrict__ x0) {
    int idx = blockIdx.x * blockDim.x + threadIdx.x;
    const int total = NN * 32;
    if (idx < total) {
        float4 v = ((const float4*)x0)[idx];
        __half2 p01 = __floats2half2_rn(v.x, v.y);
        __half2 p23 = __floats2half2_rn(v.z, v.w);
        uint2 o;
        o.x = *(unsigned int*)&p01;
        o.y = *(unsigned int*)&p23;
        g_x16A[idx] = o;
        float4 hv;
        hv.x = ALPHA_F * v.x; hv.y = ALPHA_F * v.y;
        hv.z = ALPHA_F * v.z; hv.w = ALPHA_F * v.w;
        ((float4*)g_h)[idx] = hv;
    }
    if (idx < NN) {
        g_dinv[idx] = rsqrtf((float)(g_deg[idx] + 1));   // +1 self loop
        g_cursor[idx] = 0;
    }
}

// -------------------- L3: per-block sums of deg -----------------------------
__global__ void scan1_kernel() {
    __shared__ int ws[32];
    int tid = threadIdx.x;
    int i = blockIdx.x * 1024 + tid;
    int v = (i < NN) ? g_deg[i] : 0;
    #pragma unroll
    for (int d = 16; d > 0; d >>= 1) v += __shfl_down_sync(0xffffffffu, v, d);
    if ((tid & 31) == 0) ws[tid >> 5] = v;
    __syncthreads();
    if (tid < 32) {
        int s = ws[tid];
        #pragma unroll
        for (int d = 16; d > 0; d >>= 1) s += __shfl_down_sync(0xffffffffu, s, d);
        if (tid == 0) g_bsum[blockIdx.x] = s;
    }
}

// -------------------- L4: block scan + inline prefix-of-bsums ---------------
__device__ __forceinline__ int block_scan_inc(int v, int tid) {
    __shared__ int ws[32];
    const int lane = tid & 31, wid = tid >> 5;
    int x = v;
    #pragma unroll
    for (int d = 1; d < 32; d <<= 1) {
        int y = __shfl_up_sync(0xffffffffu, x, d);
        if (lane >= d) x += y;
    }
    if (lane == 31) ws[wid] = x;
    __syncthreads();
    if (wid == 0) {
        int s = ws[lane];
        int t = s;
        #pragma unroll
        for (int d = 1; d < 32; d <<= 1) {
            int y = __shfl_up_sync(0xffffffffu, t, d);
            if (lane >= d) t += y;
        }
        ws[lane] = t - s;
    }
    __syncthreads();
    return x + ws[wid];
}

__global__ void scan2_kernel() {
    __shared__ int s_prefix;
    const int tid = threadIdx.x;
    const int bid = blockIdx.x;
    // warp 0: exclusive prefix of bsums for this block
    if (tid < 32) {
        int s = 0;
        if (tid < bid) s += g_bsum[tid];
        int j2 = tid + 32;
        if (j2 < bid) s += g_bsum[j2];
        #pragma unroll
        for (int d = 16; d > 0; d >>= 1) s += __shfl_down_sync(0xffffffffu, s, d);
        if (tid == 0) s_prefix = s;
    }
    __syncthreads();
    const int i = bid * 1024 + tid;
    int v = (i < NN) ? g_deg[i] : 0;
    int inc = block_scan_inc(v, tid);
    if (i < NN) g_rowptr[i] = inc - v + s_prefix;
    if (bid == 0 && tid == 0) g_rowptr[NN] = EE;
}

// -------------------- L5: CSR scatter ----------------------------------------
__global__ void scatter_kernel(const int* __restrict__ src,
                               const int* __restrict__ dst) {
    for (int e = blockIdx.x * blockDim.x + threadIdx.x; e < EE;
         e += gridDim.x * blockDim.x) {
        int s = src[e];
        int d = dst[e];
        int pos = g_rowptr[d] + atomicAdd(&g_cursor[d], 1);
        float w = g_dinv[s] * g_dinv[d];
        g_edge[pos] = make_int2(s, __float_as_int(w));
    }
}

// -------------------- L6..L21: hop (R2 champion form) ------------------------
__device__ __forceinline__ void acc_edge(float4& acc, uint2 r, float w) {
    float2 f01 = __half22float2(*(__half2*)&r.x);
    float2 f23 = __half22float2(*(__half2*)&r.y);
    acc.x += w * f01.x; acc.y += w * f01.y;
    acc.z += w * f23.x; acc.w += w * f23.y;
}

__global__ void __launch_bounds__(256)
hop_kernel(const uint2* __restrict__ xin, uint2* __restrict__ xout,
           float* __restrict__ h) {
    const int warp = (blockIdx.x * blockDim.x + threadIdx.x) >> 5;
    const int lane = threadIdx.x & 31;
    if (warp >= NN) return;

    const float dv = g_dinv[warp];
    uint2 xr = __ldg(&xin[warp * 32 + lane]);
    float4 acc = {0.f, 0.f, 0.f, 0.f};
    acc_edge(acc, xr, dv * dv);

    const int start = g_rowptr[warp];
    const int len   = g_deg[warp];           // edge count (no self loop)

    for (int base = 0; base < len; base += 32) {
        int idx = start + base + lane;
        int   c = 0;
        float w = 0.0f;
        if (base + lane < len) {
            int2 e = __ldg(&g_edge[idx]);
            c = e.x;
            w = __int_as_float(e.y);
        }
        int rem = len - base; if (rem > 32) rem = 32;
        int j = 0;
        for (; j + 8 <= rem; j += 8) {
            int   s0 = __shfl_sync(0xffffffffu, c, j + 0);
            int   s1 = __shfl_sync(0xffffffffu, c, j + 1);
            int   s2 = __shfl_sync(0xffffffffu, c, j + 2);
            int   s3 = __shfl_sync(0xffffffffu, c, j + 3);
            int   s4 = __shfl_sync(0xffffffffu, c, j + 4);
            int   s5 = __shfl_sync(0xffffffffu, c, j + 5);
            int   s6 = __shfl_sync(0xffffffffu, c, j + 6);
            int   s7 = __shfl_sync(0xffffffffu, c, j + 7);
            float w0 = __shfl_sync(0xffffffffu, w, j + 0);
            float w1 = __shfl_sync(0xffffffffu, w, j + 1);
            float w2 = __shfl_sync(0xffffffffu, w, j + 2);
            float w3 = __shfl_sync(0xffffffffu, w, j + 3);
            float w4 = __shfl_sync(0xffffffffu, w, j + 4);
            float w5 = __shfl_sync(0xffffffffu, w, j + 5);
            float w6 = __shfl_sync(0xffffffffu, w, j + 6);
            float w7 = __shfl_sync(0xffffffffu, w, j + 7);
            uint2 v0 = __ldg(&xin[s0 * 32 + lane]);
            uint2 v1 = __ldg(&xin[s1 * 32 + lane]);
            uint2 v2 = __ldg(&xin[s2 * 32 + lane]);
            uint2 v3 = __ldg(&xin[s3 * 32 + lane]);
            uint2 v4 = __ldg(&xin[s4 * 32 + lane]);
            uint2 v5 = __ldg(&xin[s5 * 32 + lane]);
            uint2 v6 = __ldg(&xin[s6 * 32 + lane]);
            uint2 v7 = __ldg(&xin[s7 * 32 + lane]);
            acc_edge(acc, v0, w0);
            acc_edge(acc, v1, w1);
            acc_edge(acc, v2, w2);
            acc_edge(acc, v3, w3);
            acc_edge(acc, v4, w4);
            acc_edge(acc, v5, w5);
            acc_edge(acc, v6, w6);
            acc_edge(acc, v7, w7);
        }
        for (; j < rem; j++) {
            int   s0 = __shfl_sync(0xffffffffu, c, j);
            float w0 = __shfl_sync(0xffffffffu, w, j);
            uint2 v0 = __ldg(&xin[s0 * 32 + lane]);
            acc_edge(acc, v0, w0);
        }
    }

    __half2 o01 = __floats2half2_rn(acc.x, acc.y);
    __half2 o23 = __floats2half2_rn(acc.z, acc.w);
    uint2 ow;
    ow.x = *(unsigned int*)&o01;
    ow.y = *(unsigned int*)&o23;
    xout[warp * 32 + lane] = ow;

    float4 hv = ((float4*)h)[warp * 32 + lane];
    hv.x += CW_F * acc.x; hv.y += CW_F * acc.y;
    hv.z += CW_F * acc.z; hv.w += CW_F * acc.w;
    ((float4*)h)[warp * 32 + lane] = hv;
}

// -------------------- L22: TF32 tensor-core GEMM -----------------------------
// out[n][o] = bias[o] + sum_k h[n][k] * W[o][k]
// mma.m16n8k8: A = W tile (o x k, row-major), B = h tile (k x n via col map).
#define CHUNK 64                 // nodes per chunk
#define SROW  132                // padded smem row stride (floats)

__device__ __forceinline__ unsigned f2tf32(float f) {
    unsigned r;
    asm("cvt.rna.tf32.f32 %0, %1;" : "=r"(r) : "f"(f));
    return r;
}

__global__ void __launch_bounds__(256)
gemm_mma_kernel(const float* __restrict__ h, const float* __restrict__ W,
                const float* __restrict__ bias, float* __restrict__ out) {
    __shared__ float sm[CHUNK * SROW];          // 33.8 KB, reused h-tile / C-tile

    const int tid  = threadIdx.x;
    const int wid  = tid >> 5;                  // 0..7 -> o rows [16w,16w+16)
    const int lane = tid & 31;
    const int gq   = lane >> 2;                 // group id 0..7
    const int tg   = lane & 3;                  // thread-in-group 0..3

    // A fragments: a[kt][0..3] = W rows, loaded once per block
    unsigned a[16][4];
    {
        const int o0 = wid * 16 + gq;
        #pragma unroll
        for (int kt = 0; kt < 16; kt++) {
            int k0 = kt * 8 + tg;
            a[kt][0] = f2tf32(__ldg(&W[o0 * DD + k0]));
            a[kt][1] = f2tf32(__ldg(&W[(o0 + 8) * DD + k0]));
            a[kt][2] = f2tf32(__ldg(&W[o0 * DD + k0 + 4]));
            a[kt][3] = f2tf32(__ldg(&W[(o0 + 8) * DD + k0 + 4]));
        }
    }

    for (int ci = 0; ci < 2; ci++) {
        const int node0 = (blockIdx.x * 2 + ci) * CHUNK;

        // stage h chunk -> smem (tf32-rounded), padded rows
        #pragma unroll
        for (int i = 0; i < (CHUNK * 32) / 256; i++) {
            int slot = i * 256 + tid;
            int nl = slot >> 5;
            int g4 = slot & 31;
            float4 v = __ldg(&((const float4*)h)[(node0 + nl) * 32 + g4]);
            float* p = &sm[nl * SROW + g4 * 4];
            p[0] = __uint_as_float(f2tf32(v.x));
            p[1] = __uint_as_float(f2tf32(v.y));
            p[2] = __uint_as_float(f2tf32(v.z));
            p[3] = __uint_as_float(f2tf32(v.w));
        }
        __syncthreads();

        // mma: C[nt] covers nodes [nt*8, nt*8+8) x o rows of this warp
        float c[8][4];
        #pragma unroll
        for (int nt = 0; nt < 8; nt++) {
            c[nt][0] = 0.f; c[nt][1] = 0.f; c[nt][2] = 0.f; c[nt][3] = 0.f;
            #pragma unroll
            for (int kt = 0; kt < 16; kt++) {
                unsigned b0 = __float_as_uint(sm[(nt * 8 + gq) * SROW + kt * 8 + tg]);
                unsigned b1 = __float_as_uint(sm[(nt * 8 + gq) * SROW + kt * 8 + tg + 4]);
                asm("mma.sync.aligned.m16n8k8.row.col.f32.tf32.tf32.f32 "
                    "{%0,%1,%2,%3}, {%4,%5,%6,%7}, {%8,%9}, {%0,%1,%2,%3};"
                    : "+f"(c[nt][0]), "+f"(c[nt][1]), "+f"(c[nt][2]), "+f"(c[nt][3])
                    : "r"(a[kt][0]), "r"(a[kt][1]), "r"(a[kt][2]), "r"(a[kt][3]),
                      "r"(b0), "r"(b1));
            }
        }
        __syncthreads();   // done reading h tile

        // scatter C into smem as [node][o]
        #pragma unroll
        for (int nt = 0; nt < 8; nt++) {
            int nl = nt * 8 + 2 * tg;
            int ol = wid * 16 + gq;
            sm[nl * SROW + ol]             = c[nt][0];
            sm[(nl + 1) * SROW + ol]       = c[nt][1];
            sm[nl * SROW + ol + 8]         = c[nt][2];
            sm[(nl + 1) * SROW + ol + 8]   = c[nt][3];
        }
        __syncthreads();

        // coalesced flush with bias
        #pragma unroll
        for (int i = 0; i < (CHUNK * 32) / 256; i++) {
            int slot = i * 256 + tid;
            int nl = slot >> 5;
            int o4 = slot & 31;
            int node = node0 + nl;
            if (node < NN) {
                float4 bv = __ldg(&((const float4*)bias)[o4]);
                float* p = &sm[nl * SROW + o4 * 4];
                float4 r;
                r.x = p[0] + bv.x; r.y = p[1] + bv.y;
                r.z = p[2] + bv.z; r.w = p[3] + bv.w;
                ((float4*)out)[node * 32 + o4] = r;
            }
        }
        __syncthreads();   // before next chunk overwrites smem
    }
}

// -------------------- L23: reset deg for next graph replay -------------------
__global__ void reset_kernel() {
    int v = blockIdx.x * blockDim.x + threadIdx.x;
    if (v < NN) g_deg[v] = 0;
}

// -------------------- launch -------------------------------------------------
extern "C" void kernel_launch(void* const* d_in, const int* in_sizes, int n_in,
                              void* d_out, int out_size) {
    const float* x0   = (const float*)d_in[0];
    const int*   ei   = (const int*)  d_in[1];
    const float* W    = (const float*)d_in[2];
    const float* bias = (const float*)d_in[3];
    const int* src = ei;
    const int* dst = ei + EE;
    float* out = (float*)d_out;

    void *pA, *pB, *ph;
    cudaGetSymbolAddress(&pA, g_x16A);
    cudaGetSymbolAddress(&pB, g_x16B);
    cudaGetSymbolAddress(&ph, g_h);
    uint2* xA = (uint2*)pA;
    uint2* xB = (uint2*)pB;
    float* h  = (float*)ph;

    count_deg_kernel<<<2048, 256>>>(dst);                     // L1 (deg=0 entry)
    prep_kernel<<<(NN * 32 + 255) / 256, 256>>>(x0);          // L2
    scan1_kernel<<<NBLK, 1024>>>();                           // L3
    scan2_kernel<<<NBLK, 1024>>>();                           // L4
    scatter_kernel<<<2048, 256>>>(src, dst);                  // L5

    const uint2* xin = xA;                                    // L6..L21
    uint2* xout = xB;
    for (int k = 0; k < KK; k++) {
        hop_kernel<<<(NN + 7) / 8, 256>>>(xin, xout, h);
        xin  = xout;
        xout = (xout == xB) ? xA : xB;
    }

    gemm_mma_kernel<<<NPAD / (2 * CHUNK), 256>>>(h, W, bias, out);  // L22
    reset_kernel<<<(NN + 1023) / 1024, 1024>>>();                   // L23
}

// round 12
// speedup vs baseline: 1.3062x; 1.2069x over previous
#include <cuda_runtime.h>
#include <cuda_fp16.h>

#define NN   50000
#define EE   1600000
#define DD   128
#define KK   16
#define ALPHA_F 0.05f
#define CW_F    (0.95f / 16.0f)
#define NPAD 50048
#define NBLK 49            // ceil(NN/1024)

// -------------------- scratch (static device globals; no allocs) ------------
__device__ uint2 g_x16A[NPAD * 32];     // fp16 y = dinv*x features ping
__device__ uint2 g_x16B[NPAD * 32];     // fp16 y features pong
__device__ float g_h [NPAD * DD];       // fp32 h accumulator (rows >= NN stay 0)
__device__ int   g_deg[NN];             // edge in-degree (NO self loop); 0 at entry
__device__ float g_dinv[NN];
__device__ int   g_rowptr[NN + 1];
__device__ int   g_cursor[NN];
__device__ int   g_col[EE];             // source node per CSR slot
__device__ int   g_bsum[NBLK];

// -------------------- L1: degree count (deg starts at 0) --------------------
__global__ void count_deg_kernel(const int* __restrict__ dst) {
    for (int e = blockIdx.x * blockDim.x + threadIdx.x; e < EE;
         e += gridDim.x * blockDim.x) {
        atomicAdd(&g_deg[dst[e]], 1);
    }
}

// -------------------- L2: cursor + dinv + fp16 y0 + h init ------------------
__global__ void prep_kernel(const float* __restrict__ x0) {
    int idx = blockIdx.x * blockDim.x + threadIdx.x;
    const int total = NN * 32;
    if (idx < total) {
        int node = idx >> 5;
        float dv = rsqrtf((float)(g_deg[node] + 1));    // recompute locally
        float4 v = ((const float4*)x0)[idx];
        __half2 p01 = __floats2half2_rn(dv * v.x, dv * v.y);
        __half2 p23 = __floats2half2_rn(dv * v.z, dv * v.w);
        uint2 o;
        o.x = *(unsigned int*)&p01;
        o.y = *(unsigned int*)&p23;
        g_x16A[idx] = o;
        float4 hv;
        hv.x = ALPHA_F * v.x; hv.y = ALPHA_F * v.y;
        hv.z = ALPHA_F * v.z; hv.w = ALPHA_F * v.w;
        ((float4*)g_h)[idx] = hv;
    }
    if (idx < NN) {
        g_dinv[idx] = rsqrtf((float)(g_deg[idx] + 1));   // +1 self loop
        g_cursor[idx] = 0;
    }
}

// -------------------- L3: per-block sums of deg -----------------------------
__global__ void scan1_kernel() {
    __shared__ int ws[32];
    int tid = threadIdx.x;
    int i = blockIdx.x * 1024 + tid;
    int v = (i < NN) ? g_deg[i] : 0;
    #pragma unroll
    for (int d = 16; d > 0; d >>= 1) v += __shfl_down_sync(0xffffffffu, v, d);
    if ((tid & 31) == 0) ws[tid >> 5] = v;
    __syncthreads();
    if (tid < 32) {
        int s = ws[tid];
        #pragma unroll
        for (int d = 16; d > 0; d >>= 1) s += __shfl_down_sync(0xffffffffu, s, d);
        if (tid == 0) g_bsum[blockIdx.x] = s;
    }
}

// -------------------- L4: block scan + inline prefix-of-bsums ---------------
__device__ __forceinline__ int block_scan_inc(int v, int tid) {
    __shared__ int ws[32];
    const int lane = tid & 31, wid = tid >> 5;
    int x = v;
    #pragma unroll
    for (int d = 1; d < 32; d <<= 1) {
        int y = __shfl_up_sync(0xffffffffu, x, d);
        if (lane >= d) x += y;
    }
    if (lane == 31) ws[wid] = x;
    __syncthreads();
    if (wid == 0) {
        int s = ws[lane];
        int t = s;
        #pragma unroll
        for (int d = 1; d < 32; d <<= 1) {
            int y = __shfl_up_sync(0xffffffffu, t, d);
            if (lane >= d) t += y;
        }
        ws[lane] = t - s;
    }
    __syncthreads();
    return x + ws[wid];
}

__global__ void scan2_kernel() {
    __shared__ int s_prefix;
    const int tid = threadIdx.x;
    const int bid = blockIdx.x;
    if (tid < 32) {
        int s = 0;
        if (tid < bid) s += g_bsum[tid];
        int j2 = tid + 32;
        if (j2 < bid) s += g_bsum[j2];
        #pragma unroll
        for (int d = 16; d > 0; d >>= 1) s += __shfl_down_sync(0xffffffffu, s, d);
        if (tid == 0) s_prefix = s;
    }
    __syncthreads();
    const int i = bid * 1024 + tid;
    int v = (i < NN) ? g_deg[i] : 0;
    int inc = block_scan_inc(v, tid);
    if (i < NN) g_rowptr[i] = inc - v + s_prefix;
    if (bid == 0 && tid == 0) g_rowptr[NN] = EE;
}

// -------------------- L5: CSR scatter (col only — no weight!) ---------------
__global__ void scatter_kernel(const int* __restrict__ src,
                               const int* __restrict__ dst) {
    for (int e = blockIdx.x * blockDim.x + threadIdx.x; e < EE;
         e += gridDim.x * blockDim.x) {
        int s = src[e];
        int d = dst[e];
        int pos = g_rowptr[d] + atomicAdd(&g_cursor[d], 1);
        g_col[pos] = s;
    }
}

// -------------------- L6..L21: hop on pre-scaled y --------------------------
// acc = y[d] + sum_{s in N(d)} y[s];  y_out[d] = dinv^2 * acc;  h += c*dinv*acc
__device__ __forceinline__ void acc_y(float4& acc, uint2 r) {
    float2 f01 = __half22float2(*(__half2*)&r.x);
    float2 f23 = __half22float2(*(__half2*)&r.y);
    acc.x += f01.x; acc.y += f01.y;
    acc.z += f23.x; acc.w += f23.y;
}

__global__ void __launch_bounds__(256)
hop_kernel(const uint2* __restrict__ xin, uint2* __restrict__ xout,
           float* __restrict__ h) {
    const int warp = (blockIdx.x * blockDim.x + threadIdx.x) >> 5;
    const int lane = threadIdx.x & 31;
    if (warp >= NN) return;

    uint2 xr = __ldg(&xin[warp * 32 + lane]);
    float4 acc = {0.f, 0.f, 0.f, 0.f};
    acc_y(acc, xr);                          // self term: y[d]

    const int start = g_rowptr[warp];
    const int len   = g_deg[warp];           // edge count (no self loop)

    for (int base = 0; base < len; base += 32) {
        int idx = start + base + lane;
        int c = 0;
        if (base + lane < len) c = __ldg(&g_col[idx]);
        int rem = len - base; if (rem > 32) rem = 32;
        int j = 0;
        for (; j + 8 <= rem; j += 8) {
            int s0 = __shfl_sync(0xffffffffu, c, j + 0);
            int s1 = __shfl_sync(0xffffffffu, c, j + 1);
            int s2 = __shfl_sync(0xffffffffu, c, j + 2);
            int s3 = __shfl_sync(0xffffffffu, c, j + 3);
            int s4 = __shfl_sync(0xffffffffu, c, j + 4);
            int s5 = __shfl_sync(0xffffffffu, c, j + 5);
            int s6 = __shfl_sync(0xffffffffu, c, j + 6);
            int s7 = __shfl_sync(0xffffffffu, c, j + 7);
            uint2 v0 = __ldg(&xin[s0 * 32 + lane]);
            uint2 v1 = __ldg(&xin[s1 * 32 + lane]);
            uint2 v2 = __ldg(&xin[s2 * 32 + lane]);
            uint2 v3 = __ldg(&xin[s3 * 32 + lane]);
            uint2 v4 = __ldg(&xin[s4 * 32 + lane]);
            uint2 v5 = __ldg(&xin[s5 * 32 + lane]);
            uint2 v6 = __ldg(&xin[s6 * 32 + lane]);
            uint2 v7 = __ldg(&xin[s7 * 32 + lane]);
            acc_y(acc, v0);
            acc_y(acc, v1);
            acc_y(acc, v2);
            acc_y(acc, v3);
            acc_y(acc, v4);
            acc_y(acc, v5);
            acc_y(acc, v6);
            acc_y(acc, v7);
        }
        for (; j < rem; j++) {
            int s0 = __shfl_sync(0xffffffffu, c, j);
            uint2 v0 = __ldg(&xin[s0 * 32 + lane]);
            acc_y(acc, v0);
        }
    }

    const float dv = g_dinv[warp];
    const float s2 = dv * dv;                 // y_out = dinv^2 * acc
    __half2 o01 = __floats2half2_rn(s2 * acc.x, s2 * acc.y);
    __half2 o23 = __floats2half2_rn(s2 * acc.z, s2 * acc.w);
    uint2 ow;
    ow.x = *(unsigned int*)&o01;
    ow.y = *(unsigned int*)&o23;
    xout[warp * 32 + lane] = ow;

    const float cw = CW_F * dv;               // x_out = dinv * acc
    float4 hv = ((float4*)h)[warp * 32 + lane];
    hv.x += cw * acc.x; hv.y += cw * acc.y;
    hv.z += cw * acc.z; hv.w += cw * acc.w;
    ((float4*)h)[warp * 32 + lane] = hv;
}

// -------------------- L22: TF32 tensor-core GEMM -----------------------------
// out[n][o] = bias[o] + sum_k h[n][k] * W[o][k]
#define CHUNK 64                 // nodes per chunk
#define SROW  132                // padded smem row stride (floats)

__device__ __forceinline__ unsigned f2tf32(float f) {
    unsigned r;
    asm("cvt.rna.tf32.f32 %0, %1;" : "=r"(r) : "f"(f));
    return r;
}

__global__ void __launch_bounds__(256)
gemm_mma_kernel(const float* __restrict__ h, const float* __restrict__ W,
                const float* __restrict__ bias, float* __restrict__ out) {
    __shared__ float sm[CHUNK * SROW];          // 33.8 KB, reused h-tile / C-tile

    const int tid  = threadIdx.x;
    const int wid  = tid >> 5;                  // 0..7 -> o rows [16w,16w+16)
    const int lane = tid & 31;
    const int gq   = lane >> 2;                 // group id 0..7
    const int tg   = lane & 3;                  // thread-in-group 0..3

    unsigned a[16][4];
    {
        const int o0 = wid * 16 + gq;
        #pragma unroll
        for (int kt = 0; kt < 16; kt++) {
            int k0 = kt * 8 + tg;
            a[kt][0] = f2tf32(__ldg(&W[o0 * DD + k0]));
            a[kt][1] = f2tf32(__ldg(&W[(o0 + 8) * DD + k0]));
            a[kt][2] = f2tf32(__ldg(&W[o0 * DD + k0 + 4]));
            a[kt][3] = f2tf32(__ldg(&W[(o0 + 8) * DD + k0 + 4]));
        }
    }

    for (int ci = 0; ci < 2; ci++) {
        const int node0 = (blockIdx.x * 2 + ci) * CHUNK;

        #pragma unroll
        for (int i = 0; i < (CHUNK * 32) / 256; i++) {
            int slot = i * 256 + tid;
            int nl = slot >> 5;
            int g4 = slot & 31;
            float4 v = __ldg(&((const float4*)h)[(node0 + nl) * 32 + g4]);
            float* p = &sm[nl * SROW + g4 * 4];
            p[0] = __uint_as_float(f2tf32(v.x));
            p[1] = __uint_as_float(f2tf32(v.y));
            p[2] = __uint_as_float(f2tf32(v.z));
            p[3] = __uint_as_float(f2tf32(v.w));
        }
        __syncthreads();

        float c[8][4];
        #pragma unroll
        for (int nt = 0; nt < 8; nt++) {
            c[nt][0] = 0.f; c[nt][1] = 0.f; c[nt][2] = 0.f; c[nt][3] = 0.f;
            #pragma unroll
            for (int kt = 0; kt < 16; kt++) {
                unsigned b0 = __float_as_uint(sm[(nt * 8 + gq) * SROW + kt * 8 + tg]);
                unsigned b1 = __float_as_uint(sm[(nt * 8 + gq) * SROW + kt * 8 + tg + 4]);
                asm("mma.sync.aligned.m16n8k8.row.col.f32.tf32.tf32.f32 "
                    "{%0,%1,%2,%3}, {%4,%5,%6,%7}, {%8,%9}, {%0,%1,%2,%3};"
                    : "+f"(c[nt][0]), "+f"(c[nt][1]), "+f"(c[nt][2]), "+f"(c[nt][3])
                    : "r"(a[kt][0]), "r"(a[kt][1]), "r"(a[kt][2]), "r"(a[kt][3]),
                      "r"(b0), "r"(b1));
            }
        }
        __syncthreads();

        #pragma unroll
        for (int nt = 0; nt < 8; nt++) {
            int nl = nt * 8 + 2 * tg;
            int ol = wid * 16 + gq;
            sm[nl * SROW + ol]             = c[nt][0];
            sm[(nl + 1) * SROW + ol]       = c[nt][1];
            sm[nl * SROW + ol + 8]         = c[nt][2];
            sm[(nl + 1) * SROW + ol + 8]   = c[nt][3];
        }
        __syncthreads();

        #pragma unroll
        for (int i = 0; i < (CHUNK * 32) / 256; i++) {
            int slot = i * 256 + tid;
            int nl = slot >> 5;
            int o4 = slot & 31;
            int node = node0 + nl;
            if (node < NN) {
                float4 bv = __ldg(&((const float4*)bias)[o4]);
                float* p = &sm[nl * SROW + o4 * 4];
                float4 r;
                r.x = p[0] + bv.x; r.y = p[1] + bv.y;
                r.z = p[2] + bv.z; r.w = p[3] + bv.w;
                ((float4*)out)[node * 32 + o4] = r;
            }
        }
        __syncthreads();
    }
}

// -------------------- L23: reset deg for next graph replay -------------------
__global__ void reset_kernel() {
    int v = blockIdx.x * blockDim.x + threadIdx.x;
    if (v < NN) g_deg[v] = 0;
}

// -------------------- launch -------------------------------------------------
extern "C" void kernel_launch(void* const* d_in, const int* in_sizes, int n_in,
                              void* d_out, int out_size) {
    const float* x0   = (const float*)d_in[0];
    const int*   ei   = (const int*)  d_in[1];
    const float* W    = (const float*)d_in[2];
    const float* bias = (const float*)d_in[3];
    const int* src = ei;
    const int* dst = ei + EE;
    float* out = (float*)d_out;

    void *pA, *pB, *ph;
    cudaGetSymbolAddress(&pA, g_x16A);
    cudaGetSymbolAddress(&pB, g_x16B);
    cudaGetSymbolAddress(&ph, g_h);
    uint2* xA = (uint2*)pA;
    uint2* xB = (uint2*)pB;
    float* h  = (float*)ph;

    count_deg_kernel<<<2048, 256>>>(dst);                     // L1 (deg=0 entry)
    prep_kernel<<<(NN * 32 + 255) / 256, 256>>>(x0);          // L2
    scan1_kernel<<<NBLK, 1024>>>();                           // L3
    scan2_kernel<<<NBLK, 1024>>>();                           // L4
    scatter_kernel<<<2048, 256>>>(src, dst);                  // L5

    const uint2* xin = xA;                                    // L6..L21
    uint2* xout = xB;
    for (int k = 0; k < KK; k++) {
        hop_kernel<<<(NN + 7) / 8, 256>>>(xin, xout, h);
        xin  = xout;
        xout = (xout == xB) ? xA : xB;
    }

    gemm_mma_kernel<<<NPAD / (2 * CHUNK), 256>>>(h, W, bias, out);  // L22
    reset_kernel<<<(NN + 1023) / 1024, 1024>>>();                   // L23
}